// round 16
// baseline (speedup 1.0000x reference)
#include <cuda_runtime.h>
#include <cuda_bf16.h>
#include <math.h>
#include <string.h>

// Problem constants
#define BATCH 2
#define SEQ   4096            // 16*16*16
#define CENC  512
#define CDEC  256
#define DFF   1024
#define NHEAD 8
#define HDIM  32
#define MTOT  (BATCH*SEQ)     // 8192

typedef unsigned short u16;

// ---------------- scratch (device globals; no allocation allowed) -------------
__device__ __align__(256) u16  sEncB[(size_t)BATCH*CENC*SEQ];  // bf16 [B,C,S]
__device__ __align__(256) u16  sDecB[(size_t)BATCH*CDEC*SEQ];
__device__ __align__(256) u16  sQb [MTOT*CDEC];
__device__ __align__(256) u16  sKVb[MTOT*512];      // row m = [K(256)|V(256)]
__device__ __align__(256) u16  sAOb[MTOT*CDEC];
__device__ __align__(256) float sX1[MTOT*CDEC];
__device__ __align__(256) u16  sX1b[MTOT*CDEC];
__device__ __align__(256) u16  sHb [MTOT*DFF];
__device__ __align__(256) float sEncMean[MTOT], sEncRstd[MTOT];
__device__ __align__(256) float sDecMean[MTOT], sDecRstd[MTOT];
__device__ __align__(256) float sM2[MTOT], sR2[MTOT];
// folded/converted weights (bf16) + constants (fp32)
__device__ __align__(256) u16  sWqFb [CDEC*CDEC];
__device__ __align__(256) u16  sWkvFb[CENC*512];
__device__ __align__(256) u16  sW1Fb [CDEC*DFF];
__device__ __align__(256) u16  sWoB  [CDEC*CDEC];
__device__ __align__(256) u16  sW2B  [DFF*CDEC];
__device__ __align__(256) float sC1q[CDEC],  sC2q[CDEC];
__device__ __align__(256) float sC1kv[512],  sC2kv[512];
__device__ __align__(256) float sC11[DFF],   sC21[DFF];

__device__ __forceinline__ float gelu_exact(float x) {
    return 0.5f * x * (1.0f + erff(x * 0.70710678118654752f));
}

__device__ __forceinline__ unsigned bf2_bits(float lo, float hi) {
    __nv_bfloat162 h = __floats2bfloat162_rn(lo, hi);
    unsigned u; memcpy(&u, &h, 4); return u;
}
__device__ __forceinline__ u16 bf1_bits(float x) {
    __nv_bfloat16 h = __float2bfloat16(x);
    u16 u; memcpy(&u, &h, 2); return u;
}
__device__ __forceinline__ float ex2f(float x) {
    float y; asm("ex2.approx.ftz.f32 %0, %1;" : "=f"(y) : "f"(x)); return y;
}

__device__ __forceinline__ void mma_bf16(float d[4], const unsigned a[4],
                                         const unsigned b0, const unsigned b1,
                                         const float c[4]) {
    asm volatile(
        "mma.sync.aligned.m16n8k16.row.col.f32.bf16.bf16.f32 "
        "{%0,%1,%2,%3}, {%4,%5,%6,%7}, {%8,%9}, {%10,%11,%12,%13};\n"
        : "=f"(d[0]), "=f"(d[1]), "=f"(d[2]), "=f"(d[3])
        : "r"(a[0]), "r"(a[1]), "r"(a[2]), "r"(a[3]),
          "r"(b0), "r"(b1),
          "f"(c[0]), "f"(c[1]), "f"(c[2]), "f"(c[3]));
}

__device__ __forceinline__ void ldsm4(unsigned r[4], unsigned addr) {
    asm volatile("ldmatrix.sync.aligned.m8n8.x4.shared.b16 {%0,%1,%2,%3}, [%4];\n"
        : "=r"(r[0]), "=r"(r[1]), "=r"(r[2]), "=r"(r[3]) : "r"(addr));
}
__device__ __forceinline__ void ldsm4t(unsigned r[4], unsigned addr) {
    asm volatile("ldmatrix.sync.aligned.m8n8.x4.trans.shared.b16 {%0,%1,%2,%3}, [%4];\n"
        : "=r"(r[0]), "=r"(r[1]), "=r"(r[2]), "=r"(r[3]) : "r"(addr));
}

#define CP16(dst, src) \
    asm volatile("cp.async.ca.shared.global [%0], [%1], 16;\n" :: "r"(dst), "l"(src))
#define CP_COMMIT() asm volatile("cp.async.commit_group;\n")
#define CP_WAIT1()  asm volatile("cp.async.wait_group 1;\n")

// -------- weight folding (bf16 out): Wp=diag(g)W, c1=colsum(Wp), c2=bLN@W+bias --
__device__ __forceinline__
void fold_dev(const float* __restrict__ W, const float* __restrict__ gLN,
              const float* __restrict__ bLN, const float* __restrict__ bias,
              u16* __restrict__ Wp, float* __restrict__ c1, float* __restrict__ c2,
              int K, int Nsrc, int ldp, int co, int blk) {
    __shared__ float r1[8][33], r2[8][33];
    const int tn = threadIdx.x & 31;
    const int tk = threadIdx.x >> 5;
    const int n = blk * 32 + tn;
    float s1 = 0.f, s2 = 0.f;
    #pragma unroll 4
    for (int k = tk; k < K; k += 8) {
        float w  = W[(size_t)k * Nsrc + n];
        float wp = __ldg(gLN + k) * w;
        Wp[(size_t)k * ldp + co + n] = bf1_bits(wp);
        s1 += wp;
        s2 += __ldg(bLN + k) * w;
    }
    r1[tk][tn] = s1; r2[tk][tn] = s2;
    __syncthreads();
    if (tk == 0) {
        float a1 = 0.f, a2 = 0.f;
        #pragma unroll
        for (int i = 0; i < 8; i++) { a1 += r1[i][tn]; a2 += r2[i][tn]; }
        c1[co + n] = a1;
        c2[co + n] = a2 + bias[n];
    }
}

__device__ __forceinline__
void conv_dev(const float* __restrict__ W, u16* __restrict__ Wb,
              int K, int Nsrc, int blk) {
    const int tn = threadIdx.x & 31;
    const int tk = threadIdx.x >> 5;
    const int n = blk * 32 + tn;
    #pragma unroll 4
    for (int k = tk; k < K; k += 8)
        Wb[(size_t)k * Nsrc + n] = bf1_bits(W[(size_t)k * Nsrc + n]);
}

// ------------- LN stats over channel dim + bf16 copy, [B, C, S] layout --------
template<int C>
__device__ __forceinline__
void col_stats_dev(const float* __restrict__ x, u16* __restrict__ xB,
                   float* __restrict__ mean, float* __restrict__ rstd, int idx) {
    int b = idx >> 12;
    int s = idx & (SEQ - 1);
    const float* xb = x + (size_t)b * C * SEQ + s;
    u16* xbB = xB + (size_t)b * C * SEQ + s;
    float sm = 0.f, sq = 0.f;
    #pragma unroll 8
    for (int c = 0; c < C; c++) {
        float v = xb[(size_t)c << 12];
        xbB[(size_t)c << 12] = bf1_bits(v);
        sm += v; sq += v * v;
    }
    float m = sm / C;
    mean[idx] = m;
    rstd[idx] = rsqrtf(sq / C - m * m + 1e-5f);
}

// 136 blocks: [0,72) fold/convert weights; [72,136) LN stats + bf16 copies.
// (fold and stats are independent; merging removes their serialization)
__global__ __launch_bounds__(256)
void prep_all_kernel(const float* Wq, const float* bq, const float* gDec, const float* bDec,
                     const float* Wk, const float* bk, const float* Wv, const float* bv,
                     const float* gEnc, const float* bEnc,
                     const float* W1, const float* b1, const float* gOut, const float* bOut,
                     const float* Wo, const float* W2,
                     u16* WqF, float* C1q, float* C2q,
                     u16* WkvF, float* C1kv, float* C2kv,
                     u16* W1F, float* C11, float* C21,
                     u16* WoB, u16* W2B,
                     const float* enc, const float* dec, u16* encB, u16* decB,
                     float* em, float* er, float* dm, float* dr) {
    int blk = blockIdx.x;
    if (blk < 8)
        fold_dev(Wq, gDec, bDec, bq, WqF, C1q, C2q, CDEC, CDEC, CDEC, 0, blk);
    else if (blk < 16)
        fold_dev(Wk, gEnc, bEnc, bk, WkvF, C1kv, C2kv, CENC, CDEC, 512, 0, blk - 8);
    else if (blk < 24)
        fold_dev(Wv, gEnc, bEnc, bv, WkvF, C1kv, C2kv, CENC, CDEC, 512, 256, blk - 16);
    else if (blk < 56)
        fold_dev(W1, gOut, bOut, b1, W1F, C11, C21, CDEC, DFF, DFF, 0, blk - 24);
    else if (blk < 64)
        conv_dev(Wo, WoB, CDEC, CDEC, blk - 56);
    else if (blk < 72)
        conv_dev(W2, W2B, DFF, CDEC, blk - 64);
    else {
        int idx = (blk - 72) * 256 + threadIdx.x;
        if (idx < MTOT) col_stats_dev<CENC>(enc, encB, em, er, idx);
        else            col_stats_dev<CDEC>(dec, decB, dm, dr, idx - MTOT);
    }
}

// ------------- LN stats over last dim for row-major [M, C] --------------------
__global__ void row_stats_kernel(const float* __restrict__ x,
                                 float* __restrict__ mean, float* __restrict__ rstd,
                                 int C) {
    int row  = blockIdx.x * (blockDim.x >> 5) + (threadIdx.x >> 5);
    int lane = threadIdx.x & 31;
    if (row >= MTOT) return;
    const float* xr = x + (size_t)row * C;
    float s = 0.f, q = 0.f;
    for (int c = lane; c < C; c += 32) { float v = xr[c]; s += v; q += v * v; }
    #pragma unroll
    for (int o = 16; o; o >>= 1) {
        s += __shfl_xor_sync(0xffffffffu, s, o);
        q += __shfl_xor_sync(0xffffffffu, q, o);
    }
    if (lane == 0) {
        float m = s / C;
        mean[row] = m;
        rstd[row] = rsqrtf(q / C - m * m + 1e-5f);
    }
}

// ========== bf16 mma GEMM (m16n8k16 + ldmatrix), cp.async 3-stage ==============
#define GB_BM 128
#define GB_BN 64
#define GB_BK 32
#define B_AKM 136   // AMODE0 smem stride (bf16 units)
#define B_ARM 40    // AMODE1 smem stride
#define B_WS  72    // W smem stride

template<int AMODE, int EPI, bool FOLD>
__global__ __launch_bounds__(256)
void gemm_bf16(const u16* __restrict__ A, const u16* __restrict__ W,
               const float* __restrict__ bias,
               const float* __restrict__ mean, const float* __restrict__ rstd,
               const float* __restrict__ c1, const float* __restrict__ c2,
               const float* __restrict__ res, float* __restrict__ Y,
               u16* __restrict__ Yb, int Kdim, int N) {
    constexpr int ASZ = (AMODE == 0) ? GB_BK * B_AKM : GB_BM * B_ARM;
    constexpr int WSZ = GB_BK * B_WS;
    __shared__ __align__(16) u16 sAb[3 * ASZ];
    __shared__ __align__(16) u16 sWb[3 * WSZ];

    const int tid  = threadIdx.x;
    const int warp = tid >> 5;
    const int lane = tid & 31;
    const int g = lane >> 2, t = lane & 3;
    const int m0 = blockIdx.y * GB_BM;
    const int n0 = blockIdx.x * GB_BN;
    const int bIdx = m0 >> 12;
    const int s0 = m0 & (SEQ - 1);
    const int wm = (warp & 3) * 32;
    const int wn = (warp >> 2) * 32;

    auto stage = [&](int st, int k0) {
        u16* Ab = sAb + st * ASZ;
        u16* Wb = sWb + st * WSZ;
        if (AMODE == 0) {
            const u16* Xb = A + (size_t)bIdx * Kdim * SEQ + s0;
            #pragma unroll
            for (int i = 0; i < 2; i++) {
                int c = tid + i * 256;
                int kk = c >> 4, mm8 = (c & 15) * 8;
                CP16((unsigned)__cvta_generic_to_shared(Ab + kk * B_AKM + mm8),
                     Xb + (size_t)(k0 + kk) * SEQ + mm8);
            }
        } else {
            #pragma unroll
            for (int i = 0; i < 2; i++) {
                int c = tid + i * 256;
                int mm = c >> 2, k8 = (c & 3) * 8;
                CP16((unsigned)__cvta_generic_to_shared(Ab + mm * B_ARM + k8),
                     A + (size_t)(m0 + mm) * Kdim + k0 + k8);
            }
        }
        {
            int kk = tid >> 3, nn8 = (tid & 7) * 8;
            CP16((unsigned)__cvta_generic_to_shared(Wb + kk * B_WS + nn8),
                 W + (size_t)(k0 + kk) * N + n0 + nn8);
        }
    };

    const int nK = Kdim / GB_BK;
    stage(0, 0);      CP_COMMIT();
    stage(1, GB_BK);  CP_COMMIT();

    float acc[2][4][4] = {};

    for (int i = 0; i < nK; i++) {
        CP_WAIT1();
        __syncthreads();
        if (i + 2 < nK) stage((i + 2) % 3, (i + 2) * GB_BK);
        CP_COMMIT();

        const unsigned aBase = (unsigned)__cvta_generic_to_shared(sAb + (i % 3) * ASZ);
        const unsigned wBase = (unsigned)__cvta_generic_to_shared(sWb + (i % 3) * WSZ);

        #pragma unroll
        for (int kc = 0; kc < 2; kc++) {
            unsigned a[2][4];
            #pragma unroll
            for (int mf = 0; mf < 2; mf++) {
                if (AMODE == 0) {
                    int krow = kc * 16 + (lane & 7) + ((lane & 16) >> 1);
                    int mcol = wm + mf * 16 + ((lane & 8) ? 8 : 0);
                    ldsm4t(a[mf], aBase + (krow * B_AKM + mcol) * 2);
                } else {
                    int mrow = wm + mf * 16 + (lane & 15);
                    int kcol = kc * 16 + ((lane & 16) ? 8 : 0);
                    ldsm4(a[mf], aBase + (mrow * B_ARM + kcol) * 2);
                }
            }
            #pragma unroll
            for (int pair = 0; pair < 2; pair++) {
                int wrow = kc * 16 + (lane & 15);
                int wcol = wn + pair * 16 + ((lane & 16) ? 8 : 0);
                unsigned wb[4];
                ldsm4t(wb, wBase + (wrow * B_WS + wcol) * 2);
                mma_bf16(acc[0][pair * 2],     a[0], wb[0], wb[1], acc[0][pair * 2]);
                mma_bf16(acc[1][pair * 2],     a[1], wb[0], wb[1], acc[1][pair * 2]);
                mma_bf16(acc[0][pair * 2 + 1], a[0], wb[2], wb[3], acc[0][pair * 2 + 1]);
                mma_bf16(acc[1][pair * 2 + 1], a[1], wb[2], wb[3], acc[1][pair * 2 + 1]);
            }
        }
        // (no trailing barrier: next iter's top barrier provides the ordering)
    }

    // ---- epilogue ----
    #pragma unroll
    for (int mf = 0; mf < 2; mf++) {
        int row0 = m0 + wm + mf * 16 + g;
        int row1 = row0 + 8;
        float al0 = 1.f, be0 = 0.f, al1 = 1.f, be1 = 0.f;
        if (FOLD) {
            al0 = rstd[row0]; be0 = -mean[row0] * al0;
            al1 = rstd[row1]; be1 = -mean[row1] * al1;
        }
        #pragma unroll
        for (int nf = 0; nf < 4; nf++) {
            int col = n0 + wn + nf * 8 + 2 * t;
            float bx, by, c1x = 0.f, c1y = 0.f;
            if (FOLD) {
                bx = c2[col]; by = c2[col + 1];
                c1x = c1[col]; c1y = c1[col + 1];
            } else {
                bx = bias[col]; by = bias[col + 1];
            }
            float v0 = acc[mf][nf][0] * al0 + be0 * c1x + bx;
            float v1 = acc[mf][nf][1] * al0 + be0 * c1y + by;
            float v2 = acc[mf][nf][2] * al1 + be1 * c1x + bx;
            float v3 = acc[mf][nf][3] * al1 + be1 * c1y + by;
            if (EPI == 2) {
                *(unsigned*)(Yb + (size_t)row0 * N + col) =
                    bf2_bits(gelu_exact(v0), gelu_exact(v1));
                *(unsigned*)(Yb + (size_t)row1 * N + col) =
                    bf2_bits(gelu_exact(v2), gelu_exact(v3));
            } else if (EPI == 3) {
                int sr0 = row0 & (SEQ - 1), sr1 = row1 & (SEQ - 1);
                float2 rr0 = *(const float2*)(res + (size_t)row0 * N + col);
                float2 rr1 = *(const float2*)(res + (size_t)row1 * N + col);
                float* y0 = Y + ((size_t)bIdx * N + col) * SEQ;
                float* y1 = Y + ((size_t)bIdx * N + col + 1) * SEQ;
                y0[sr0] = v0 + rr0.x;  y1[sr0] = v1 + rr0.y;
                y0[sr1] = v2 + rr1.x;  y1[sr1] = v3 + rr1.y;
            } else if (EPI == 4) {
                *(unsigned*)(Yb + (size_t)row0 * N + col) = bf2_bits(v0, v1);
                *(unsigned*)(Yb + (size_t)row1 * N + col) = bf2_bits(v2, v3);
            } else {   // EPI 5
                int sr0 = row0 & (SEQ - 1), sr1 = row1 & (SEQ - 1);
                const float* r0p = res + ((size_t)bIdx * N + col) * SEQ;
                const float* r1p = res + ((size_t)bIdx * N + col + 1) * SEQ;
                v0 += r0p[sr0]; v1 += r1p[sr0];
                v2 += r0p[sr1]; v3 += r1p[sr1];
                *(float2*)(Y + (size_t)row0 * N + col) = make_float2(v0, v1);
                *(float2*)(Y + (size_t)row1 * N + col) = make_float2(v2, v3);
                *(unsigned*)(Yb + (size_t)row0 * N + col) = bf2_bits(v0, v1);
                *(unsigned*)(Yb + (size_t)row1 * N + col) = bf2_bits(v2, v3);
            }
        }
    }
}

// ------ Flash attention: bf16 mma, P in registers (round-13 proven, FA_BN=64) --
#define FA_BM 128
#define FA_BN 64
#define KVSTR 40

__global__ __launch_bounds__(256)
void flash_bf16_kernel(const u16* __restrict__ Q, const u16* __restrict__ KV,
                       u16* __restrict__ O) {
    __shared__ __align__(16) u16 KsB[2][FA_BN * KVSTR];
    __shared__ __align__(16) u16 VsB[2][FA_BN * KVSTR];

    const int tid  = threadIdx.x;
    const int warp = tid >> 5;
    const int lane = tid & 31;
    const int g = lane >> 2, t = lane & 3;
    const int bh = blockIdx.y;
    const int b = bh >> 3, h = bh & 7;
    const int q0 = blockIdx.x * FA_BM;
    const float sc2 = 0.17677669529663687f * 1.4426950408889634f;  // scale*log2(e)

    unsigned qa[2][4];
    {
        const u16* Qh = Q + ((size_t)b * SEQ + q0 + warp * 16) * CDEC + h * HDIM;
        #pragma unroll
        for (int kc = 0; kc < 2; kc++) {
            qa[kc][0] = *(const unsigned*)(Qh + (size_t)g       * CDEC + kc * 16 + 2 * t);
            qa[kc][1] = *(const unsigned*)(Qh + (size_t)(g + 8) * CDEC + kc * 16 + 2 * t);
            qa[kc][2] = *(const unsigned*)(Qh + (size_t)g       * CDEC + kc * 16 + 2 * t + 8);
            qa[kc][3] = *(const unsigned*)(Qh + (size_t)(g + 8) * CDEC + kc * 16 + 2 * t + 8);
        }
    }

    float l0 = 0.f, l1 = 0.f;
    float o[4][4] = {};
    const u16* Kp = KV + (size_t)b * SEQ * 512 + h * HDIM;
    const u16* Vp = Kp + 256;

    auto stageKV = [&](int buf, int kt) {
        int r  = tid >> 2;
        int c8 = (tid & 3) * 8;
        const u16* krow = Kp + (size_t)(kt * FA_BN + r) * 512 + c8;
        const u16* vrow = Vp + (size_t)(kt * FA_BN + r) * 512 + c8;
        CP16((unsigned)__cvta_generic_to_shared(&KsB[buf][r * KVSTR + c8]), krow);
        CP16((unsigned)__cvta_generic_to_shared(&VsB[buf][r * KVSTR + c8]), vrow);
    };

    const int nT = SEQ / FA_BN;
    stageKV(0, 0); CP_COMMIT();

    for (int kt = 0; kt < nT; kt++) {
        if (kt + 1 < nT) stageKV((kt + 1) & 1, kt + 1);
        CP_COMMIT();
        CP_WAIT1();
        __syncthreads();

        const unsigned ksBase = (unsigned)__cvta_generic_to_shared(KsB[kt & 1]);
        const unsigned vsBase = (unsigned)__cvta_generic_to_shared(VsB[kt & 1]);

        // ---- S = Q K^T with exp fused per n-tile pair; P packed to registers
        unsigned pp[8][2];
        float ls0 = 0.f, ls1 = 0.f;
        #pragma unroll
        for (int ntp = 0; ntp < 4; ntp++) {
            int krow = ntp * 16 + (lane & 15);
            int csel = (lane & 16) ? 8 : 0;
            unsigned b0[4], b1[4];
            ldsm4(b0, ksBase + (krow * KVSTR + 0  + csel) * 2);
            ldsm4(b1, ksBase + (krow * KVSTR + 16 + csel) * 2);
            float c0[4] = {0.f, 0.f, 0.f, 0.f}, c1[4] = {0.f, 0.f, 0.f, 0.f};
            mma_bf16(c0, qa[0], b0[0], b0[2], c0);
            mma_bf16(c0, qa[1], b1[0], b1[2], c0);
            mma_bf16(c1, qa[0], b0[1], b0[3], c1);
            mma_bf16(c1, qa[1], b1[1], b1[3], c1);
            float p0 = ex2f(c0[0] * sc2), p1 = ex2f(c0[1] * sc2);
            float p2 = ex2f(c0[2] * sc2), p3 = ex2f(c0[3] * sc2);
            ls0 += p0 + p1; ls1 += p2 + p3;
            pp[2 * ntp][0] = bf2_bits(p0, p1);
            pp[2 * ntp][1] = bf2_bits(p2, p3);
            p0 = ex2f(c1[0] * sc2); p1 = ex2f(c1[1] * sc2);
            p2 = ex2f(c1[2] * sc2); p3 = ex2f(c1[3] * sc2);
            ls0 += p0 + p1; ls1 += p2 + p3;
            pp[2 * ntp + 1][0] = bf2_bits(p0, p1);
            pp[2 * ntp + 1][1] = bf2_bits(p2, p3);
        }
        ls0 += __shfl_xor_sync(0xffffffffu, ls0, 1);
        ls0 += __shfl_xor_sync(0xffffffffu, ls0, 2);
        ls1 += __shfl_xor_sync(0xffffffffu, ls1, 1);
        ls1 += __shfl_xor_sync(0xffffffffu, ls1, 2);
        l0 += ls0;
        l1 += ls1;

        // ---- O += P V (A operand from registers) ----
        #pragma unroll
        for (int kc = 0; kc < 4; kc++) {
            unsigned pa[4];
            pa[0] = pp[2 * kc][0];
            pa[1] = pp[2 * kc][1];
            pa[2] = pp[2 * kc + 1][0];
            pa[3] = pp[2 * kc + 1][1];
            #pragma unroll
            for (int ntp = 0; ntp < 2; ntp++) {
                int vrow = kc * 16 + (lane & 15);
                int vcol = ntp * 16 + ((lane & 16) ? 8 : 0);
                unsigned vb[4];
                ldsm4t(vb, vsBase + (vrow * KVSTR + vcol) * 2);
                mma_bf16(o[2 * ntp],     pa, vb[0], vb[1], o[2 * ntp]);
                mma_bf16(o[2 * ntp + 1], pa, vb[2], vb[3], o[2 * ntp + 1]);
            }
        }
        __syncthreads();
    }

    float inv0 = 1.0f / l0, inv1 = 1.0f / l1;
    u16* Op0 = O + ((size_t)b * SEQ + q0 + warp * 16 + g) * CDEC + h * HDIM;
    u16* Op1 = Op0 + 8 * CDEC;
    #pragma unroll
    for (int nt = 0; nt < 4; nt++) {
        *(unsigned*)(Op0 + nt * 8 + 2 * t) = bf2_bits(o[nt][0] * inv0, o[nt][1] * inv0);
        *(unsigned*)(Op1 + nt * 8 + 2 * t) = bf2_bits(o[nt][2] * inv1, o[nt][3] * inv1);
    }
}

// ------------------------------ launcher --------------------------------------
extern "C" void kernel_launch(void* const* d_in, const int* in_sizes, int n_in,
                              void* d_out, int out_size) {
    const float* enc   = (const float*)d_in[0];
    const float* dec   = (const float*)d_in[1];
    const float* Wq    = (const float*)d_in[2];
    const float* bq    = (const float*)d_in[3];
    const float* Wk    = (const float*)d_in[4];
    const float* bk    = (const float*)d_in[5];
    const float* Wv    = (const float*)d_in[6];
    const float* bv    = (const float*)d_in[7];
    const float* Wo    = (const float*)d_in[8];
    const float* bo    = (const float*)d_in[9];
    const float* gEnc  = (const float*)d_in[10];
    const float* bEnc  = (const float*)d_in[11];
    const float* gDec  = (const float*)d_in[12];
    const float* bDec  = (const float*)d_in[13];
    const float* gOut  = (const float*)d_in[14];
    const float* bOut  = (const float*)d_in[15];
    const float* W1    = (const float*)d_in[16];
    const float* b1    = (const float*)d_in[17];
    const float* W2    = (const float*)d_in[18];
    const float* b2    = (const float*)d_in[19];
    float* out = (float*)d_out;

    u16 *pEncB, *pDecB, *pQb, *pKVb, *pAOb, *pX1b, *pHb;
    u16 *pWqFb, *pWkvFb, *pW1Fb, *pWoB, *pW2B;
    float *pX1, *pEm, *pEr, *pDm, *pDr, *pM2, *pR2;
    float *pC1q, *pC2q, *pC1kv, *pC2kv, *pC11, *pC21;
    cudaGetSymbolAddress((void**)&pEncB, sEncB);
    cudaGetSymbolAddress((void**)&pDecB, sDecB);
    cudaGetSymbolAddress((void**)&pQb,   sQb);
    cudaGetSymbolAddress((void**)&pKVb,  sKVb);
    cudaGetSymbolAddress((void**)&pAOb,  sAOb);
    cudaGetSymbolAddress((void**)&pX1,   sX1);
    cudaGetSymbolAddress((void**)&pX1b,  sX1b);
    cudaGetSymbolAddress((void**)&pHb,   sHb);
    cudaGetSymbolAddress((void**)&pEm,   sEncMean);
    cudaGetSymbolAddress((void**)&pEr,   sEncRstd);
    cudaGetSymbolAddress((void**)&pDm,   sDecMean);
    cudaGetSymbolAddress((void**)&pDr,   sDecRstd);
    cudaGetSymbolAddress((void**)&pM2,   sM2);
    cudaGetSymbolAddress((void**)&pR2,   sR2);
    cudaGetSymbolAddress((void**)&pWqFb, sWqFb);
    cudaGetSymbolAddress((void**)&pWkvFb,sWkvFb);
    cudaGetSymbolAddress((void**)&pW1Fb, sW1Fb);
    cudaGetSymbolAddress((void**)&pWoB,  sWoB);
    cudaGetSymbolAddress((void**)&pW2B,  sW2B);
    cudaGetSymbolAddress((void**)&pC1q,  sC1q);
    cudaGetSymbolAddress((void**)&pC2q,  sC2q);
    cudaGetSymbolAddress((void**)&pC1kv, sC1kv);
    cudaGetSymbolAddress((void**)&pC2kv, sC2kv);
    cudaGetSymbolAddress((void**)&pC11,  sC11);
    cudaGetSymbolAddress((void**)&pC21,  sC21);

    // 0. fold/convert weights + LN stats + bf16 activation copies (one launch)
    prep_all_kernel<<<136, 256>>>(Wq, bq, gDec, bDec, Wk, bk, Wv, bv, gEnc, bEnc,
                                  W1, b1, gOut, bOut, Wo, W2,
                                  pWqFb, pC1q, pC2q, pWkvFb, pC1kv, pC2kv,
                                  pW1Fb, pC11, pC21, pWoB, pW2B,
                                  enc, dec, pEncB, pDecB, pEm, pEr, pDm, pDr);

    // 1. Q projection + fused KV projection (bf16 in/out, LN folded)
    gemm_bf16<0,4,true><<<dim3(CDEC / GB_BN, MTOT / GB_BM), 256>>>(
        pDecB, pWqFb, nullptr, pDm, pDr, pC1q, pC2q, nullptr, nullptr, pQb, CDEC, CDEC);
    gemm_bf16<0,4,true><<<dim3(512 / GB_BN, MTOT / GB_BM), 256>>>(
        pEncB, pWkvFb, nullptr, pEm, pEr, pC1kv, pC2kv, nullptr, nullptr, pKVb, CENC, 512);

    // 2. Flash attention (P in registers, fused ex2)
    flash_bf16_kernel<<<dim3(SEQ / FA_BM, BATCH * NHEAD), 256>>>(pQb, pKVb, pAOb);

    // 3. Output projection + residual: x1 (fp32) + x1b (bf16)
    gemm_bf16<1,5,false><<<dim3(CDEC / GB_BN, MTOT / GB_BM), 256>>>(
        pAOb, pWoB, bo, nullptr, nullptr, nullptr, nullptr, dec, pX1, pX1b, CDEC, CDEC);

    // 4. LN2 stats on fp32 x1
    row_stats_kernel<<<MTOT / 8, 256>>>(pX1, pM2, pR2, CDEC);

    // 5. FFN1: gelu(LN2(x1) @ W1 + b1) -> bf16 hidden (LN + b1 folded)
    gemm_bf16<1,2,true><<<dim3(DFF / GB_BN, MTOT / GB_BM), 256>>>(
        pX1b, pW1Fb, nullptr, pM2, pR2, pC11, pC21, nullptr, nullptr, pHb, CDEC, DFF);

    // 6. FFN2 + residual + transposed [B,C,S] fp32 output write
    gemm_bf16<1,3,false><<<dim3(CDEC / GB_BN, MTOT / GB_BM), 256>>>(
        pHb, pW2B, b2, nullptr, nullptr, nullptr, nullptr, pX1, out, nullptr, DFF, CDEC);
}

// round 17
// speedup vs baseline: 1.5379x; 1.5379x over previous
#include <cuda_runtime.h>
#include <cuda_bf16.h>
#include <math.h>
#include <string.h>

// Problem constants
#define BATCH 2
#define SEQ   4096            // 16*16*16
#define CENC  512
#define CDEC  256
#define DFF   1024
#define NHEAD 8
#define HDIM  32
#define MTOT  (BATCH*SEQ)     // 8192

typedef unsigned short u16;

// ---------------- scratch (device globals; no allocation allowed) -------------
__device__ __align__(256) u16  sEncB[(size_t)BATCH*CENC*SEQ];  // bf16 [B,C,S]
__device__ __align__(256) u16  sDecB[(size_t)BATCH*CDEC*SEQ];
__device__ __align__(256) u16  sQb [MTOT*CDEC];
__device__ __align__(256) u16  sKVb[MTOT*512];      // row m = [K(256)|V(256)]
__device__ __align__(256) u16  sAOb[MTOT*CDEC];
__device__ __align__(256) float sX1[MTOT*CDEC];
__device__ __align__(256) u16  sX1b[MTOT*CDEC];
__device__ __align__(256) u16  sHb [MTOT*DFF];
__device__ __align__(256) float sEncMean[MTOT], sEncRstd[MTOT];
__device__ __align__(256) float sDecMean[MTOT], sDecRstd[MTOT];
__device__ __align__(256) float sM2[MTOT], sR2[MTOT];
// folded/converted weights (bf16) + constants (fp32)
__device__ __align__(256) u16  sWqFb [CDEC*CDEC];
__device__ __align__(256) u16  sWkvFb[CENC*512];
__device__ __align__(256) u16  sW1Fb [CDEC*DFF];
__device__ __align__(256) u16  sWoB  [CDEC*CDEC];
__device__ __align__(256) u16  sW2B  [DFF*CDEC];
__device__ __align__(256) float sC1q[CDEC],  sC2q[CDEC];
__device__ __align__(256) float sC1kv[512],  sC2kv[512];
__device__ __align__(256) float sC11[DFF],   sC21[DFF];

__device__ __forceinline__ float gelu_exact(float x) {
    return 0.5f * x * (1.0f + erff(x * 0.70710678118654752f));
}

__device__ __forceinline__ unsigned bf2_bits(float lo, float hi) {
    __nv_bfloat162 h = __floats2bfloat162_rn(lo, hi);
    unsigned u; memcpy(&u, &h, 4); return u;
}
__device__ __forceinline__ u16 bf1_bits(float x) {
    __nv_bfloat16 h = __float2bfloat16(x);
    u16 u; memcpy(&u, &h, 2); return u;
}
__device__ __forceinline__ float ex2f(float x) {
    float y; asm("ex2.approx.ftz.f32 %0, %1;" : "=f"(y) : "f"(x)); return y;
}

__device__ __forceinline__ void mma_bf16(float d[4], const unsigned a[4],
                                         const unsigned b0, const unsigned b1,
                                         const float c[4]) {
    asm volatile(
        "mma.sync.aligned.m16n8k16.row.col.f32.bf16.bf16.f32 "
        "{%0,%1,%2,%3}, {%4,%5,%6,%7}, {%8,%9}, {%10,%11,%12,%13};\n"
        : "=f"(d[0]), "=f"(d[1]), "=f"(d[2]), "=f"(d[3])
        : "r"(a[0]), "r"(a[1]), "r"(a[2]), "r"(a[3]),
          "r"(b0), "r"(b1),
          "f"(c[0]), "f"(c[1]), "f"(c[2]), "f"(c[3]));
}

__device__ __forceinline__ void ldsm4(unsigned r[4], unsigned addr) {
    asm volatile("ldmatrix.sync.aligned.m8n8.x4.shared.b16 {%0,%1,%2,%3}, [%4];\n"
        : "=r"(r[0]), "=r"(r[1]), "=r"(r[2]), "=r"(r[3]) : "r"(addr));
}
__device__ __forceinline__ void ldsm4t(unsigned r[4], unsigned addr) {
    asm volatile("ldmatrix.sync.aligned.m8n8.x4.trans.shared.b16 {%0,%1,%2,%3}, [%4];\n"
        : "=r"(r[0]), "=r"(r[1]), "=r"(r[2]), "=r"(r[3]) : "r"(addr));
}

#define CP16(dst, src) \
    asm volatile("cp.async.ca.shared.global [%0], [%1], 16;\n" :: "r"(dst), "l"(src))
#define CP_COMMIT() asm volatile("cp.async.commit_group;\n")
#define CP_WAIT1()  asm volatile("cp.async.wait_group 1;\n")

// -------- weight folding (bf16 out): Wp=diag(g)W, c1=colsum(Wp), c2=bLN@W+bias --
__device__ __forceinline__
void fold_dev(const float* __restrict__ W, const float* __restrict__ gLN,
              const float* __restrict__ bLN, const float* __restrict__ bias,
              u16* __restrict__ Wp, float* __restrict__ c1, float* __restrict__ c2,
              int K, int Nsrc, int ldp, int co, int blk) {
    __shared__ float r1[8][33], r2[8][33];
    const int tn = threadIdx.x & 31;
    const int tk = threadIdx.x >> 5;
    const int n = blk * 32 + tn;
    float s1 = 0.f, s2 = 0.f;
    #pragma unroll 4
    for (int k = tk; k < K; k += 8) {
        float w  = W[(size_t)k * Nsrc + n];
        float wp = __ldg(gLN + k) * w;
        Wp[(size_t)k * ldp + co + n] = bf1_bits(wp);
        s1 += wp;
        s2 += __ldg(bLN + k) * w;
    }
    r1[tk][tn] = s1; r2[tk][tn] = s2;
    __syncthreads();
    if (tk == 0) {
        float a1 = 0.f, a2 = 0.f;
        #pragma unroll
        for (int i = 0; i < 8; i++) { a1 += r1[i][tn]; a2 += r2[i][tn]; }
        c1[co + n] = a1;
        c2[co + n] = a2 + bias[n];
    }
}

__device__ __forceinline__
void conv_dev(const float* __restrict__ W, u16* __restrict__ Wb,
              int K, int Nsrc, int blk) {
    const int tn = threadIdx.x & 31;
    const int tk = threadIdx.x >> 5;
    const int n = blk * 32 + tn;
    #pragma unroll 4
    for (int k = tk; k < K; k += 8)
        Wb[(size_t)k * Nsrc + n] = bf1_bits(W[(size_t)k * Nsrc + n]);
}

// 72 blocks: 8 Wq + 8 Wk + 8 Wv + 32 W1 + 8 Wo(conv) + 8 W2(conv)
__global__ __launch_bounds__(256)
void fold_all_kernel(const float* Wq, const float* bq, const float* gDec, const float* bDec,
                     const float* Wk, const float* bk, const float* Wv, const float* bv,
                     const float* gEnc, const float* bEnc,
                     const float* W1, const float* b1, const float* gOut, const float* bOut,
                     const float* Wo, const float* W2,
                     u16* WqF, float* C1q, float* C2q,
                     u16* WkvF, float* C1kv, float* C2kv,
                     u16* W1F, float* C11, float* C21,
                     u16* WoB, u16* W2B) {
    int blk = blockIdx.x;
    if (blk < 8)
        fold_dev(Wq, gDec, bDec, bq, WqF, C1q, C2q, CDEC, CDEC, CDEC, 0, blk);
    else if (blk < 16)
        fold_dev(Wk, gEnc, bEnc, bk, WkvF, C1kv, C2kv, CENC, CDEC, 512, 0, blk - 8);
    else if (blk < 24)
        fold_dev(Wv, gEnc, bEnc, bv, WkvF, C1kv, C2kv, CENC, CDEC, 512, 256, blk - 16);
    else if (blk < 56)
        fold_dev(W1, gOut, bOut, b1, W1F, C11, C21, CDEC, DFF, DFF, 0, blk - 24);
    else if (blk < 64)
        conv_dev(Wo, WoB, CDEC, CDEC, blk - 56);
    else
        conv_dev(W2, W2B, DFF, CDEC, blk - 64);
}

// ------------- LN stats over channel dim + bf16 copy, [B, C, S] layout --------
template<int C>
__device__ __forceinline__
void col_stats_dev(const float* __restrict__ x, u16* __restrict__ xB,
                   float* __restrict__ mean, float* __restrict__ rstd, int idx) {
    int b = idx >> 12;
    int s = idx & (SEQ - 1);
    const float* xb = x + (size_t)b * C * SEQ + s;
    u16* xbB = xB + (size_t)b * C * SEQ + s;
    float sm = 0.f, sq = 0.f;
    #pragma unroll 8
    for (int c = 0; c < C; c++) {
        float v = xb[(size_t)c << 12];
        xbB[(size_t)c << 12] = bf1_bits(v);
        sm += v; sq += v * v;
    }
    float m = sm / C;
    mean[idx] = m;
    rstd[idx] = rsqrtf(sq / C - m * m + 1e-5f);
}

__global__ void stats_all_kernel(const float* __restrict__ enc, const float* __restrict__ dec,
                                 u16* encB, u16* decB,
                                 float* em, float* er, float* dm, float* dr) {
    int idx = blockIdx.x * blockDim.x + threadIdx.x;
    if (idx < MTOT) col_stats_dev<CENC>(enc, encB, em, er, idx);
    else            col_stats_dev<CDEC>(dec, decB, dm, dr, idx - MTOT);
}

// ------------- LN stats over last dim for row-major [M, C] --------------------
__global__ void row_stats_kernel(const float* __restrict__ x,
                                 float* __restrict__ mean, float* __restrict__ rstd,
                                 int C) {
    int row  = blockIdx.x * (blockDim.x >> 5) + (threadIdx.x >> 5);
    int lane = threadIdx.x & 31;
    if (row >= MTOT) return;
    const float* xr = x + (size_t)row * C;
    float s = 0.f, q = 0.f;
    for (int c = lane; c < C; c += 32) { float v = xr[c]; s += v; q += v * v; }
    #pragma unroll
    for (int o = 16; o; o >>= 1) {
        s += __shfl_xor_sync(0xffffffffu, s, o);
        q += __shfl_xor_sync(0xffffffffu, q, o);
    }
    if (lane == 0) {
        float m = s / C;
        mean[row] = m;
        rstd[row] = rsqrtf(q / C - m * m + 1e-5f);
    }
}

// ========== bf16 mma GEMM (m16n8k16 + ldmatrix), cp.async 3-stage ==============
// AMODE 0: A(m,k) = Xb16[b, k, s] ([B,C,S] bf16)  -> smem [k][m]
// AMODE 1: A(m,k) = A[m*K+k] (row-major bf16)     -> smem [m][k]
// FOLD: v = rstd_m*acc - mean_m*rstd_m*c1_n + c2_n (c2 includes bias)
// EPI 2: Yb[m,n] = bf16(gelu(v))
// EPI 3: Y[b,n,s] = v + bias[n] + res[m,n]  (fp32 transposed out)
// EPI 4: Yb[m,n] = bf16(v)
// EPI 5: Y[m,n] = v + bias[n] + res[b,n,s] (fp32) AND Yb[m,n] = bf16(same)
#define GB_BM 128
#define GB_BN 64
#define GB_BK 32
#define B_AKM 136   // AMODE0 smem stride (bf16 units)
#define B_ARM 40    // AMODE1 smem stride
#define B_WS  72    // W smem stride

template<int AMODE, int EPI, bool FOLD>
__global__ __launch_bounds__(256)
void gemm_bf16(const u16* __restrict__ A, const u16* __restrict__ W,
               const float* __restrict__ bias,
               const float* __restrict__ mean, const float* __restrict__ rstd,
               const float* __restrict__ c1, const float* __restrict__ c2,
               const float* __restrict__ res, float* __restrict__ Y,
               u16* __restrict__ Yb, int Kdim, int N) {
    constexpr int ASZ = (AMODE == 0) ? GB_BK * B_AKM : GB_BM * B_ARM;
    constexpr int WSZ = GB_BK * B_WS;
    __shared__ __align__(16) u16 sAb[3 * ASZ];
    __shared__ __align__(16) u16 sWb[3 * WSZ];

    const int tid  = threadIdx.x;
    const int warp = tid >> 5;
    const int lane = tid & 31;
    const int g = lane >> 2, t = lane & 3;
    const int m0 = blockIdx.y * GB_BM;
    const int n0 = blockIdx.x * GB_BN;
    const int bIdx = m0 >> 12;
    const int s0 = m0 & (SEQ - 1);
    const int wm = (warp & 3) * 32;
    const int wn = (warp >> 2) * 32;

    auto stage = [&](int st, int k0) {
        u16* Ab = sAb + st * ASZ;
        u16* Wb = sWb + st * WSZ;
        if (AMODE == 0) {
            const u16* Xb = A + (size_t)bIdx * Kdim * SEQ + s0;
            #pragma unroll
            for (int i = 0; i < 2; i++) {
                int c = tid + i * 256;
                int kk = c >> 4, mm8 = (c & 15) * 8;
                CP16((unsigned)__cvta_generic_to_shared(Ab + kk * B_AKM + mm8),
                     Xb + (size_t)(k0 + kk) * SEQ + mm8);
            }
        } else {
            #pragma unroll
            for (int i = 0; i < 2; i++) {
                int c = tid + i * 256;
                int mm = c >> 2, k8 = (c & 3) * 8;
                CP16((unsigned)__cvta_generic_to_shared(Ab + mm * B_ARM + k8),
                     A + (size_t)(m0 + mm) * Kdim + k0 + k8);
            }
        }
        {
            int kk = tid >> 3, nn8 = (tid & 7) * 8;
            CP16((unsigned)__cvta_generic_to_shared(Wb + kk * B_WS + nn8),
                 W + (size_t)(k0 + kk) * N + n0 + nn8);
        }
    };

    const int nK = Kdim / GB_BK;
    stage(0, 0);      CP_COMMIT();
    stage(1, GB_BK);  CP_COMMIT();

    float acc[2][4][4] = {};

    for (int i = 0; i < nK; i++) {
        CP_WAIT1();
        __syncthreads();
        if (i + 2 < nK) stage((i + 2) % 3, (i + 2) * GB_BK);
        CP_COMMIT();

        const unsigned aBase = (unsigned)__cvta_generic_to_shared(sAb + (i % 3) * ASZ);
        const unsigned wBase = (unsigned)__cvta_generic_to_shared(sWb + (i % 3) * WSZ);

        #pragma unroll
        for (int kc = 0; kc < 2; kc++) {
            unsigned a[2][4];
            #pragma unroll
            for (int mf = 0; mf < 2; mf++) {
                if (AMODE == 0) {
                    int krow = kc * 16 + (lane & 7) + ((lane & 16) >> 1);
                    int mcol = wm + mf * 16 + ((lane & 8) ? 8 : 0);
                    ldsm4t(a[mf], aBase + (krow * B_AKM + mcol) * 2);
                } else {
                    int mrow = wm + mf * 16 + (lane & 15);
                    int kcol = kc * 16 + ((lane & 16) ? 8 : 0);
                    ldsm4(a[mf], aBase + (mrow * B_ARM + kcol) * 2);
                }
            }
            #pragma unroll
            for (int pair = 0; pair < 2; pair++) {
                int wrow = kc * 16 + (lane & 15);
                int wcol = wn + pair * 16 + ((lane & 16) ? 8 : 0);
                unsigned wb[4];
                ldsm4t(wb, wBase + (wrow * B_WS + wcol) * 2);
                mma_bf16(acc[0][pair * 2],     a[0], wb[0], wb[1], acc[0][pair * 2]);
                mma_bf16(acc[1][pair * 2],     a[1], wb[0], wb[1], acc[1][pair * 2]);
                mma_bf16(acc[0][pair * 2 + 1], a[0], wb[2], wb[3], acc[0][pair * 2 + 1]);
                mma_bf16(acc[1][pair * 2 + 1], a[1], wb[2], wb[3], acc[1][pair * 2 + 1]);
            }
        }
        __syncthreads();
    }

    // ---- epilogue ----
    #pragma unroll
    for (int mf = 0; mf < 2; mf++) {
        int row0 = m0 + wm + mf * 16 + g;
        int row1 = row0 + 8;
        float al0 = 1.f, be0 = 0.f, al1 = 1.f, be1 = 0.f;
        if (FOLD) {
            al0 = rstd[row0]; be0 = -mean[row0] * al0;
            al1 = rstd[row1]; be1 = -mean[row1] * al1;
        }
        #pragma unroll
        for (int nf = 0; nf < 4; nf++) {
            int col = n0 + wn + nf * 8 + 2 * t;
            float bx, by, c1x = 0.f, c1y = 0.f;
            if (FOLD) {
                bx = c2[col]; by = c2[col + 1];
                c1x = c1[col]; c1y = c1[col + 1];
            } else {
                bx = bias[col]; by = bias[col + 1];
            }
            float v0 = acc[mf][nf][0] * al0 + be0 * c1x + bx;
            float v1 = acc[mf][nf][1] * al0 + be0 * c1y + by;
            float v2 = acc[mf][nf][2] * al1 + be1 * c1x + bx;
            float v3 = acc[mf][nf][3] * al1 + be1 * c1y + by;
            if (EPI == 2) {
                *(unsigned*)(Yb + (size_t)row0 * N + col) =
                    bf2_bits(gelu_exact(v0), gelu_exact(v1));
                *(unsigned*)(Yb + (size_t)row1 * N + col) =
                    bf2_bits(gelu_exact(v2), gelu_exact(v3));
            } else if (EPI == 3) {
                int sr0 = row0 & (SEQ - 1), sr1 = row1 & (SEQ - 1);
                float2 rr0 = *(const float2*)(res + (size_t)row0 * N + col);
                float2 rr1 = *(const float2*)(res + (size_t)row1 * N + col);
                float* y0 = Y + ((size_t)bIdx * N + col) * SEQ;
                float* y1 = Y + ((size_t)bIdx * N + col + 1) * SEQ;
                y0[sr0] = v0 + rr0.x;  y1[sr0] = v1 + rr0.y;
                y0[sr1] = v2 + rr1.x;  y1[sr1] = v3 + rr1.y;
            } else if (EPI == 4) {
                *(unsigned*)(Yb + (size_t)row0 * N + col) = bf2_bits(v0, v1);
                *(unsigned*)(Yb + (size_t)row1 * N + col) = bf2_bits(v2, v3);
            } else {   // EPI 5
                int sr0 = row0 & (SEQ - 1), sr1 = row1 & (SEQ - 1);
                const float* r0p = res + ((size_t)bIdx * N + col) * SEQ;
                const float* r1p = res + ((size_t)bIdx * N + col + 1) * SEQ;
                v0 += r0p[sr0]; v1 += r1p[sr0];
                v2 += r0p[sr1]; v3 += r1p[sr1];
                *(float2*)(Y + (size_t)row0 * N + col) = make_float2(v0, v1);
                *(float2*)(Y + (size_t)row1 * N + col) = make_float2(v2, v3);
                *(unsigned*)(Yb + (size_t)row0 * N + col) = bf2_bits(v0, v1);
                *(unsigned*)(Yb + (size_t)row1 * N + col) = bf2_bits(v2, v3);
            }
        }
    }
}

// ------ Flash attention: bf16 mma, P in registers (exp fused into S loop) -----
#define FA_BM 128
#define FA_BN 64
#define KVSTR 40

__global__ __launch_bounds__(256)
void flash_bf16_kernel(const u16* __restrict__ Q, const u16* __restrict__ KV,
                       u16* __restrict__ O) {
    __shared__ __align__(16) u16 KsB[2][FA_BN * KVSTR];
    __shared__ __align__(16) u16 VsB[2][FA_BN * KVSTR];

    const int tid  = threadIdx.x;
    const int warp = tid >> 5;
    const int lane = tid & 31;
    const int g = lane >> 2, t = lane & 3;
    const int bh = blockIdx.y;
    const int b = bh >> 3, h = bh & 7;
    const int q0 = blockIdx.x * FA_BM;
    const float sc2 = 0.17677669529663687f * 1.4426950408889634f;  // scale*log2(e)

    unsigned qa[2][4];
    {
        const u16* Qh = Q + ((size_t)b * SEQ + q0 + warp * 16) * CDEC + h * HDIM;
        #pragma unroll
        for (int kc = 0; kc < 2; kc++) {
            qa[kc][0] = *(const unsigned*)(Qh + (size_t)g       * CDEC + kc * 16 + 2 * t);
            qa[kc][1] = *(const unsigned*)(Qh + (size_t)(g + 8) * CDEC + kc * 16 + 2 * t);
            qa[kc][2] = *(const unsigned*)(Qh + (size_t)g       * CDEC + kc * 16 + 2 * t + 8);
            qa[kc][3] = *(const unsigned*)(Qh + (size_t)(g + 8) * CDEC + kc * 16 + 2 * t + 8);
        }
    }

    float l0 = 0.f, l1 = 0.f;
    float o[4][4] = {};
    const u16* Kp = KV + (size_t)b * SEQ * 512 + h * HDIM;
    const u16* Vp = Kp + 256;

    auto stageKV = [&](int buf, int kt) {
        int r  = tid >> 2;
        int c8 = (tid & 3) * 8;
        const u16* krow = Kp + (size_t)(kt * FA_BN + r) * 512 + c8;
        const u16* vrow = Vp + (size_t)(kt * FA_BN + r) * 512 + c8;
        CP16((unsigned)__cvta_generic_to_shared(&KsB[buf][r * KVSTR + c8]), krow);
        CP16((unsigned)__cvta_generic_to_shared(&VsB[buf][r * KVSTR + c8]), vrow);
    };

    const int nT = SEQ / FA_BN;
    stageKV(0, 0); CP_COMMIT();

    for (int kt = 0; kt < nT; kt++) {
        if (kt + 1 < nT) stageKV((kt + 1) & 1, kt + 1);
        CP_COMMIT();
        CP_WAIT1();
        __syncthreads();

        const unsigned ksBase = (unsigned)__cvta_generic_to_shared(KsB[kt & 1]);
        const unsigned vsBase = (unsigned)__cvta_generic_to_shared(VsB[kt & 1]);

        // ---- S = Q K^T with exp fused per n-tile pair; P packed to registers
        unsigned pp[8][2];
        float ls0 = 0.f, ls1 = 0.f;
        #pragma unroll
        for (int ntp = 0; ntp < 4; ntp++) {
            int krow = ntp * 16 + (lane & 15);
            int csel = (lane & 16) ? 8 : 0;
            unsigned b0[4], b1[4];
            ldsm4(b0, ksBase + (krow * KVSTR + 0  + csel) * 2);
            ldsm4(b1, ksBase + (krow * KVSTR + 16 + csel) * 2);
            float c0[4] = {0.f, 0.f, 0.f, 0.f}, c1[4] = {0.f, 0.f, 0.f, 0.f};
            mma_bf16(c0, qa[0], b0[0], b0[2], c0);
            mma_bf16(c0, qa[1], b1[0], b1[2], c0);
            mma_bf16(c1, qa[0], b0[1], b0[3], c1);
            mma_bf16(c1, qa[1], b1[1], b1[3], c1);
            float p0 = ex2f(c0[0] * sc2), p1 = ex2f(c0[1] * sc2);
            float p2 = ex2f(c0[2] * sc2), p3 = ex2f(c0[3] * sc2);
            ls0 += p0 + p1; ls1 += p2 + p3;
            pp[2 * ntp][0] = bf2_bits(p0, p1);
            pp[2 * ntp][1] = bf2_bits(p2, p3);
            p0 = ex2f(c1[0] * sc2); p1 = ex2f(c1[1] * sc2);
            p2 = ex2f(c1[2] * sc2); p3 = ex2f(c1[3] * sc2);
            ls0 += p0 + p1; ls1 += p2 + p3;
            pp[2 * ntp + 1][0] = bf2_bits(p0, p1);
            pp[2 * ntp + 1][1] = bf2_bits(p2, p3);
        }
        ls0 += __shfl_xor_sync(0xffffffffu, ls0, 1);
        ls0 += __shfl_xor_sync(0xffffffffu, ls0, 2);
        ls1 += __shfl_xor_sync(0xffffffffu, ls1, 1);
        ls1 += __shfl_xor_sync(0xffffffffu, ls1, 2);
        l0 += ls0;
        l1 += ls1;

        // ---- O += P V (A operand from registers) ----
        #pragma unroll
        for (int kc = 0; kc < 4; kc++) {
            unsigned pa[4];
            pa[0] = pp[2 * kc][0];
            pa[1] = pp[2 * kc][1];
            pa[2] = pp[2 * kc + 1][0];
            pa[3] = pp[2 * kc + 1][1];
            #pragma unroll
            for (int ntp = 0; ntp < 2; ntp++) {
                int vrow = kc * 16 + (lane & 15);
                int vcol = ntp * 16 + ((lane & 16) ? 8 : 0);
                unsigned vb[4];
                ldsm4t(vb, vsBase + (vrow * KVSTR + vcol) * 2);
                mma_bf16(o[2 * ntp],     pa, vb[0], vb[1], o[2 * ntp]);
                mma_bf16(o[2 * ntp + 1], pa, vb[2], vb[3], o[2 * ntp + 1]);
            }
        }
        __syncthreads();
    }

    float inv0 = 1.0f / l0, inv1 = 1.0f / l1;
    u16* Op0 = O + ((size_t)b * SEQ + q0 + warp * 16 + g) * CDEC + h * HDIM;
    u16* Op1 = Op0 + 8 * CDEC;
    #pragma unroll
    for (int nt = 0; nt < 4; nt++) {
        *(unsigned*)(Op0 + nt * 8 + 2 * t) = bf2_bits(o[nt][0] * inv0, o[nt][1] * inv0);
        *(unsigned*)(Op1 + nt * 8 + 2 * t) = bf2_bits(o[nt][2] * inv1, o[nt][3] * inv1);
    }
}

// ------------------------------ launcher --------------------------------------
extern "C" void kernel_launch(void* const* d_in, const int* in_sizes, int n_in,
                              void* d_out, int out_size) {
    const float* enc   = (const float*)d_in[0];
    const float* dec   = (const float*)d_in[1];
    const float* Wq    = (const float*)d_in[2];
    const float* bq    = (const float*)d_in[3];
    const float* Wk    = (const float*)d_in[4];
    const float* bk    = (const float*)d_in[5];
    const float* Wv    = (const float*)d_in[6];
    const float* bv    = (const float*)d_in[7];
    const float* Wo    = (const float*)d_in[8];
    const float* bo    = (const float*)d_in[9];
    const float* gEnc  = (const float*)d_in[10];
    const float* bEnc  = (const float*)d_in[11];
    const float* gDec  = (const float*)d_in[12];
    const float* bDec  = (const float*)d_in[13];
    const float* gOut  = (const float*)d_in[14];
    const float* bOut  = (const float*)d_in[15];
    const float* W1    = (const float*)d_in[16];
    const float* b1    = (const float*)d_in[17];
    const float* W2    = (const float*)d_in[18];
    const float* b2    = (const float*)d_in[19];
    float* out = (float*)d_out;

    u16 *pEncB, *pDecB, *pQb, *pKVb, *pAOb, *pX1b, *pHb;
    u16 *pWqFb, *pWkvFb, *pW1Fb, *pWoB, *pW2B;
    float *pX1, *pEm, *pEr, *pDm, *pDr, *pM2, *pR2;
    float *pC1q, *pC2q, *pC1kv, *pC2kv, *pC11, *pC21;
    cudaGetSymbolAddress((void**)&pEncB, sEncB);
    cudaGetSymbolAddress((void**)&pDecB, sDecB);
    cudaGetSymbolAddress((void**)&pQb,   sQb);
    cudaGetSymbolAddress((void**)&pKVb,  sKVb);
    cudaGetSymbolAddress((void**)&pAOb,  sAOb);
    cudaGetSymbolAddress((void**)&pX1,   sX1);
    cudaGetSymbolAddress((void**)&pX1b,  sX1b);
    cudaGetSymbolAddress((void**)&pHb,   sHb);
    cudaGetSymbolAddress((void**)&pEm,   sEncMean);
    cudaGetSymbolAddress((void**)&pEr,   sEncRstd);
    cudaGetSymbolAddress((void**)&pDm,   sDecMean);
    cudaGetSymbolAddress((void**)&pDr,   sDecRstd);
    cudaGetSymbolAddress((void**)&pM2,   sM2);
    cudaGetSymbolAddress((void**)&pR2,   sR2);
    cudaGetSymbolAddress((void**)&pWqFb, sWqFb);
    cudaGetSymbolAddress((void**)&pWkvFb,sWkvFb);
    cudaGetSymbolAddress((void**)&pW1Fb, sW1Fb);
    cudaGetSymbolAddress((void**)&pWoB,  sWoB);
    cudaGetSymbolAddress((void**)&pW2B,  sW2B);
    cudaGetSymbolAddress((void**)&pC1q,  sC1q);
    cudaGetSymbolAddress((void**)&pC2q,  sC2q);
    cudaGetSymbolAddress((void**)&pC1kv, sC1kv);
    cudaGetSymbolAddress((void**)&pC2kv, sC2kv);
    cudaGetSymbolAddress((void**)&pC11,  sC11);
    cudaGetSymbolAddress((void**)&pC21,  sC21);

    // 0. fold/convert weights + LN stats (with bf16 activation copies)
    fold_all_kernel<<<72, 256>>>(Wq, bq, gDec, bDec, Wk, bk, Wv, bv, gEnc, bEnc,
                                 W1, b1, gOut, bOut, Wo, W2,
                                 pWqFb, pC1q, pC2q, pWkvFb, pC1kv, pC2kv,
                                 pW1Fb, pC11, pC21, pWoB, pW2B);
    stats_all_kernel<<<64, 256>>>(enc, dec, pEncB, pDecB, pEm, pEr, pDm, pDr);

    // 1. Q projection + fused KV projection (bf16 in/out, LN folded)
    gemm_bf16<0,4,true><<<dim3(CDEC / GB_BN, MTOT / GB_BM), 256>>>(
        pDecB, pWqFb, nullptr, pDm, pDr, pC1q, pC2q, nullptr, nullptr, pQb, CDEC, CDEC);
    gemm_bf16<0,4,true><<<dim3(512 / GB_BN, MTOT / GB_BM), 256>>>(
        pEncB, pWkvFb, nullptr, pEm, pEr, pC1kv, pC2kv, nullptr, nullptr, pKVb, CENC, 512);

    // 2. Flash attention (P in registers, fused ex2)
    flash_bf16_kernel<<<dim3(SEQ / FA_BM, BATCH * NHEAD), 256>>>(pQb, pKVb, pAOb);

    // 3. Output projection + residual: x1 (fp32) + x1b (bf16)
    gemm_bf16<1,5,false><<<dim3(CDEC / GB_BN, MTOT / GB_BM), 256>>>(
        pAOb, pWoB, bo, nullptr, nullptr, nullptr, nullptr, dec, pX1, pX1b, CDEC, CDEC);

    // 4. LN2 stats on fp32 x1
    row_stats_kernel<<<MTOT / 8, 256>>>(pX1, pM2, pR2, CDEC);

    // 5. FFN1: gelu(LN2(x1) @ W1 + b1) -> bf16 hidden (LN + b1 folded)
    gemm_bf16<1,2,true><<<dim3(DFF / GB_BN, MTOT / GB_BM), 256>>>(
        pX1b, pW1Fb, nullptr, pM2, pR2, pC11, pC21, nullptr, nullptr, pHb, CDEC, DFF);

    // 6. FFN2 + residual + transposed [B,C,S] fp32 output write
    gemm_bf16<1,3,false><<<dim3(CDEC / GB_BN, MTOT / GB_BM), 256>>>(
        pHb, pW2B, b2, nullptr, nullptr, nullptr, nullptr, pX1, out, nullptr, DFF, CDEC);
}